// round 4
// baseline (speedup 1.0000x reference)
#include <cuda_runtime.h>
#include <cuda_bf16.h>
#include <math.h>

#define N_NODES    500000
#define NUM_GRAPHS 1024

// Scratch (no cudaMalloc allowed). BSS-zeroed at load; self-cleaning per call.
__device__ float g_agg [N_NODES * 4];      // 8 MB, L2-resident
__device__ float g_sums[NUM_GRAPHS * 4];
__device__ float g_cnts[NUM_GRAPHS];

// ---------------------------------------------------------------------------
// Kernel 1: edge scatter  agg[dst] += x[src]
// 8 edges/thread: 2x int4 streaming index loads per side, 8 independent L2
// gathers in flight, one red.v4 (1 sector) per edge. L2-sector bound.
// ---------------------------------------------------------------------------
__global__ void __launch_bounds__(256) k_edge(const float4* __restrict__ x,
                                              const int*    __restrict__ src,
                                              const int*    __restrict__ dst,
                                              int E) {
    int q  = blockIdx.x * blockDim.x + threadIdx.x;   // octet index
    int Eo = E >> 3;                                   // full octets

    if (q < Eo) {
        const int4* s4p = reinterpret_cast<const int4*>(src) + 2 * q;
        const int4* d4p = reinterpret_cast<const int4*>(dst) + 2 * q;
        int4 sa = __ldcs(s4p);
        int4 sb = __ldcs(s4p + 1);
        int4 da = __ldcs(d4p);
        int4 db = __ldcs(d4p + 1);

        float4 v0 = __ldg(x + sa.x);
        float4 v1 = __ldg(x + sa.y);
        float4 v2 = __ldg(x + sa.z);
        float4 v3 = __ldg(x + sa.w);
        float4 v4 = __ldg(x + sb.x);
        float4 v5 = __ldg(x + sb.y);
        float4 v6 = __ldg(x + sb.z);
        float4 v7 = __ldg(x + sb.w);

        #define RED4(didx, v)                                                  \
            asm volatile("red.global.add.v4.f32 [%0], {%1, %2, %3, %4};"       \
                         :: "l"(&g_agg[(size_t)(didx) * 4]),                    \
                            "f"((v).x), "f"((v).y), "f"((v).z), "f"((v).w)      \
                         : "memory")
        RED4(da.x, v0); RED4(da.y, v1); RED4(da.z, v2); RED4(da.w, v3);
        RED4(db.x, v4); RED4(db.y, v5); RED4(db.z, v6); RED4(db.w, v7);
        #undef RED4
    } else if (q == Eo) {
        for (int i = Eo * 8; i < E; i++) {
            int s = __ldg(src + i);
            int d = __ldg(dst + i);
            float4 v = __ldg(x + s);
            asm volatile("red.global.add.v4.f32 [%0], {%1, %2, %3, %4};"
                         :: "l"(&g_agg[(size_t)d * 4]),
                            "f"(v.x), "f"(v.y), "f"(v.z), "f"(v.w) : "memory");
        }
    }
}

// ---------------------------------------------------------------------------
// Kernel 2: per-node MLP + pooled sum. 4 nodes/thread: accumulate locally
// (nodes in a thread almost always share a graph id since ~488 nodes/graph),
// flush rare intra-thread graph boundaries via direct atomics, then ONE
// warp-segmented scan over per-thread suffix partials.
// Self-cleaning: zeroes g_agg after consuming it.
// ---------------------------------------------------------------------------
__device__ __forceinline__ void mlp4(float h0, float h1, float h2, float h3,
                                     const float* sW1, const float* sb1,
                                     const float* sW2, const float* sb2,
                                     float o[4]) {
    float a[4];
    #pragma unroll
    for (int k = 0; k < 4; k++) a[k] = sb2[k];
    #pragma unroll
    for (int j = 0; j < 16; j++) {
        float tj = sb1[j]
                 + h0 * sW1[0 * 16 + j]
                 + h1 * sW1[1 * 16 + j]
                 + h2 * sW1[2 * 16 + j]
                 + h3 * sW1[3 * 16 + j];
        tj = fmaxf(tj, 0.0f);
        #pragma unroll
        for (int k = 0; k < 4; k++) a[k] += tj * sW2[j * 4 + k];
    }
    #pragma unroll
    for (int k = 0; k < 4; k++) o[k] = fmaxf(a[k], 0.0f);
}

__global__ void __launch_bounds__(256) k_node(const float4* __restrict__ x,
                       const int*    __restrict__ batch,
                       const float*  __restrict__ eps_p,
                       const float*  __restrict__ W1,   // [4,16]
                       const float*  __restrict__ b1,   // [16]
                       const float*  __restrict__ W2,   // [16,4]
                       const float*  __restrict__ b2) { // [4]
    __shared__ float sW1[64], sb1[16], sW2[64], sb2[4];
    __shared__ float seps;
    int t = threadIdx.x;
    if (t < 64)  sW1[t] = W1[t];
    if (t < 16)  sb1[t] = b1[t];
    if (t >= 64 && t < 128) sW2[t - 64] = W2[t - 64];
    if (t >= 128 && t < 132) sb2[t - 128] = b2[t - 128];
    if (t == 132) seps = 1.0f + eps_p[0];
    __syncthreads();

    int q = blockIdx.x * blockDim.x + threadIdx.x;   // quad-node index
    int base = q * 4;

    // per-thread running segment (suffix): graph id + accumulated outputs
    float a0 = 0.f, a1 = 0.f, a2 = 0.f, a3 = 0.f, ac = 0.f;
    int gcur = -1;

    if (base < N_NODES) {
        int nmax = N_NODES - base;
        if (nmax > 4) nmax = 4;
        int4 b4;
        if (nmax == 4) {
            b4 = __ldg(reinterpret_cast<const int4*>(batch) + q);
        } else {
            b4.x = b4.y = b4.z = b4.w = -1;
            int* bp = &b4.x;
            for (int n = 0; n < nmax; n++) bp[n] = __ldg(batch + base + n);
        }
        const int bids[4] = {b4.x, b4.y, b4.z, b4.w};
        float4* aggv = reinterpret_cast<float4*>(g_agg);
        float se = seps;

        #pragma unroll
        for (int n = 0; n < 4; n++) {
            if (n >= nmax) break;
            float4 xv = __ldg(x + base + n);
            float4 av = aggv[base + n];
            aggv[base + n] = make_float4(0.f, 0.f, 0.f, 0.f);
            float o[4];
            mlp4(se * xv.x + av.x, se * xv.y + av.y,
                 se * xv.z + av.z, se * xv.w + av.w,
                 sW1, sb1, sW2, sb2, o);
            int g = bids[n];
            if (g != gcur) {
                if (gcur >= 0) {   // rare intra-thread boundary: flush directly
                    atomicAdd(&g_sums[gcur * 4 + 0], a0);
                    atomicAdd(&g_sums[gcur * 4 + 1], a1);
                    atomicAdd(&g_sums[gcur * 4 + 2], a2);
                    atomicAdd(&g_sums[gcur * 4 + 3], a3);
                    atomicAdd(&g_cnts[gcur], ac);
                }
                gcur = g; a0 = a1 = a2 = a3 = ac = 0.f;
            }
            a0 += o[0]; a1 += o[1]; a2 += o[2]; a3 += o[3]; ac += 1.0f;
        }
    }

    // Warp-segmented inclusive sum over per-thread suffix partials.
    unsigned lane = threadIdx.x & 31u;
    #pragma unroll
    for (int off = 1; off < 32; off <<= 1) {
        int   gg = __shfl_up_sync(0xFFFFFFFFu, gcur, off);
        float t0 = __shfl_up_sync(0xFFFFFFFFu, a0,   off);
        float t1 = __shfl_up_sync(0xFFFFFFFFu, a1,   off);
        float t2 = __shfl_up_sync(0xFFFFFFFFu, a2,   off);
        float t3 = __shfl_up_sync(0xFFFFFFFFu, a3,   off);
        float tc = __shfl_up_sync(0xFFFFFFFFu, ac,   off);
        if (lane >= (unsigned)off && gg == gcur) {
            a0 += t0; a1 += t1; a2 += t2; a3 += t3; ac += tc;
        }
    }
    int gnext = __shfl_down_sync(0xFFFFFFFFu, gcur, 1);
    bool last = (lane == 31u) || (gnext != gcur);
    if (last && gcur >= 0) {
        atomicAdd(&g_sums[gcur * 4 + 0], a0);
        atomicAdd(&g_sums[gcur * 4 + 1], a1);
        atomicAdd(&g_sums[gcur * 4 + 2], a2);
        atomicAdd(&g_sums[gcur * 4 + 3], a3);
        atomicAdd(&g_cnts[gcur], ac);
    }
}

// ---------------------------------------------------------------------------
// Kernel 3: mean pool + log_softmax; zeroes g_sums/g_cnts after consuming.
// ---------------------------------------------------------------------------
__global__ void k_pool(float* __restrict__ out) {
    int g = blockIdx.x * blockDim.x + threadIdx.x;
    if (g >= NUM_GRAPHS) return;
    float c = fmaxf(g_cnts[g], 1.0f);
    g_cnts[g] = 0.0f;
    float v[4];
    float m = -INFINITY;
    #pragma unroll
    for (int k = 0; k < 4; k++) {
        v[k] = g_sums[g * 4 + k] / c;
        g_sums[g * 4 + k] = 0.0f;
        m = fmaxf(m, v[k]);
    }
    float s = 0.0f;
    #pragma unroll
    for (int k = 0; k < 4; k++) s += expf(v[k] - m);
    float l = m + logf(s);
    #pragma unroll
    for (int k = 0; k < 4; k++) out[g * 4 + k] = v[k] - l;
}

// ---------------------------------------------------------------------------
extern "C" void kernel_launch(void* const* d_in, const int* in_sizes, int n_in,
                              void* d_out, int out_size) {
    const float4* x   = (const float4*)d_in[0];
    const int*    ei  = (const int*)   d_in[1];   // [2, E]
    const int*    bat = (const int*)   d_in[2];
    const float*  eps = (const float*) d_in[3];
    const float*  W1  = (const float*) d_in[4];
    const float*  b1  = (const float*) d_in[5];
    const float*  W2  = (const float*) d_in[6];
    const float*  b2  = (const float*) d_in[7];
    float* out = (float*)d_out;

    int E = in_sizes[1] / 2;
    const int* src = ei;
    const int* dst = ei + E;

    int octs  = E / 8 + 1;                  // +1 thread for the tail
    int quads = (N_NODES + 3) / 4;
    k_edge<<<(octs + 255) / 256, 256>>>(x, src, dst, E);
    k_node<<<(quads + 255) / 256, 256>>>(x, bat, eps, W1, b1, W2, b2);
    k_pool<<<(NUM_GRAPHS + 255) / 256, 256>>>(out);
}

// round 5
// speedup vs baseline: 1.0021x; 1.0021x over previous
#include <cuda_runtime.h>
#include <cuda_bf16.h>
#include <math.h>

#define N_NODES    500000
#define NUM_GRAPHS 1024

// Scratch (no cudaMalloc allowed). BSS-zeroed at load; self-cleaning per call.
__device__ float g_agg [N_NODES * 4];      // 8 MB, L2-resident
__device__ float g_sums[NUM_GRAPHS * 4];
__device__ float g_cnts[NUM_GRAPHS];

// ---------------------------------------------------------------------------
// Kernel 1: edge scatter  agg[dst] += x[src]
// 8 edges/thread: 2x int4 streaming index loads per side, 8 independent L2
// gathers in flight, one red.v4 (1 sector) per edge. L2-sector bound.
// ---------------------------------------------------------------------------
__global__ void __launch_bounds__(256) k_edge(const float4* __restrict__ x,
                                              const int*    __restrict__ src,
                                              const int*    __restrict__ dst,
                                              int E) {
    int q  = blockIdx.x * blockDim.x + threadIdx.x;   // octet index
    int Eo = E >> 3;                                   // full octets

    if (q < Eo) {
        const int4* s4p = reinterpret_cast<const int4*>(src) + 2 * q;
        const int4* d4p = reinterpret_cast<const int4*>(dst) + 2 * q;
        int4 sa = __ldcs(s4p);
        int4 sb = __ldcs(s4p + 1);
        int4 da = __ldcs(d4p);
        int4 db = __ldcs(d4p + 1);

        float4 v0 = __ldg(x + sa.x);
        float4 v1 = __ldg(x + sa.y);
        float4 v2 = __ldg(x + sa.z);
        float4 v3 = __ldg(x + sa.w);
        float4 v4 = __ldg(x + sb.x);
        float4 v5 = __ldg(x + sb.y);
        float4 v6 = __ldg(x + sb.z);
        float4 v7 = __ldg(x + sb.w);

        #define RED4(didx, v)                                                  \
            asm volatile("red.global.add.v4.f32 [%0], {%1, %2, %3, %4};"       \
                         :: "l"(&g_agg[(size_t)(didx) * 4]),                    \
                            "f"((v).x), "f"((v).y), "f"((v).z), "f"((v).w)      \
                         : "memory")
        RED4(da.x, v0); RED4(da.y, v1); RED4(da.z, v2); RED4(da.w, v3);
        RED4(db.x, v4); RED4(db.y, v5); RED4(db.z, v6); RED4(db.w, v7);
        #undef RED4
    } else if (q == Eo) {
        for (int i = Eo * 8; i < E; i++) {
            int s = __ldg(src + i);
            int d = __ldg(dst + i);
            float4 v = __ldg(x + s);
            asm volatile("red.global.add.v4.f32 [%0], {%1, %2, %3, %4};"
                         :: "l"(&g_agg[(size_t)d * 4]),
                            "f"(v.x), "f"(v.y), "f"(v.z), "f"(v.w) : "memory");
        }
    }
}

// ---------------------------------------------------------------------------
// Kernel 2: per-node MLP + pooled sum. 4 nodes/thread: accumulate locally
// (nodes in a thread almost always share a graph id since ~488 nodes/graph),
// flush rare intra-thread graph boundaries via direct atomics, then ONE
// warp-segmented scan over per-thread suffix partials.
// Self-cleaning: zeroes g_agg after consuming it.
// ---------------------------------------------------------------------------
__device__ __forceinline__ void mlp4(float h0, float h1, float h2, float h3,
                                     const float* sW1, const float* sb1,
                                     const float* sW2, const float* sb2,
                                     float o[4]) {
    float a[4];
    #pragma unroll
    for (int k = 0; k < 4; k++) a[k] = sb2[k];
    #pragma unroll
    for (int j = 0; j < 16; j++) {
        float tj = sb1[j]
                 + h0 * sW1[0 * 16 + j]
                 + h1 * sW1[1 * 16 + j]
                 + h2 * sW1[2 * 16 + j]
                 + h3 * sW1[3 * 16 + j];
        tj = fmaxf(tj, 0.0f);
        #pragma unroll
        for (int k = 0; k < 4; k++) a[k] += tj * sW2[j * 4 + k];
    }
    #pragma unroll
    for (int k = 0; k < 4; k++) o[k] = fmaxf(a[k], 0.0f);
}

__global__ void __launch_bounds__(256) k_node(const float4* __restrict__ x,
                       const int*    __restrict__ batch,
                       const float*  __restrict__ eps_p,
                       const float*  __restrict__ W1,   // [4,16]
                       const float*  __restrict__ b1,   // [16]
                       const float*  __restrict__ W2,   // [16,4]
                       const float*  __restrict__ b2) { // [4]
    __shared__ float sW1[64], sb1[16], sW2[64], sb2[4];
    __shared__ float seps;
    int t = threadIdx.x;
    if (t < 64)  sW1[t] = W1[t];
    if (t < 16)  sb1[t] = b1[t];
    if (t >= 64 && t < 128) sW2[t - 64] = W2[t - 64];
    if (t >= 128 && t < 132) sb2[t - 128] = b2[t - 128];
    if (t == 132) seps = 1.0f + eps_p[0];
    __syncthreads();

    int q = blockIdx.x * blockDim.x + threadIdx.x;   // quad-node index
    int base = q * 4;

    // per-thread running segment (suffix): graph id + accumulated outputs
    float a0 = 0.f, a1 = 0.f, a2 = 0.f, a3 = 0.f, ac = 0.f;
    int gcur = -1;

    if (base < N_NODES) {
        int nmax = N_NODES - base;
        if (nmax > 4) nmax = 4;
        int4 b4;
        if (nmax == 4) {
            b4 = __ldg(reinterpret_cast<const int4*>(batch) + q);
        } else {
            b4.x = b4.y = b4.z = b4.w = -1;
            int* bp = &b4.x;
            for (int n = 0; n < nmax; n++) bp[n] = __ldg(batch + base + n);
        }
        const int bids[4] = {b4.x, b4.y, b4.z, b4.w};
        float4* aggv = reinterpret_cast<float4*>(g_agg);
        float se = seps;

        #pragma unroll
        for (int n = 0; n < 4; n++) {
            if (n >= nmax) break;
            float4 xv = __ldg(x + base + n);
            float4 av = aggv[base + n];
            aggv[base + n] = make_float4(0.f, 0.f, 0.f, 0.f);
            float o[4];
            mlp4(se * xv.x + av.x, se * xv.y + av.y,
                 se * xv.z + av.z, se * xv.w + av.w,
                 sW1, sb1, sW2, sb2, o);
            int g = bids[n];
            if (g != gcur) {
                if (gcur >= 0) {   // rare intra-thread boundary: flush directly
                    atomicAdd(&g_sums[gcur * 4 + 0], a0);
                    atomicAdd(&g_sums[gcur * 4 + 1], a1);
                    atomicAdd(&g_sums[gcur * 4 + 2], a2);
                    atomicAdd(&g_sums[gcur * 4 + 3], a3);
                    atomicAdd(&g_cnts[gcur], ac);
                }
                gcur = g; a0 = a1 = a2 = a3 = ac = 0.f;
            }
            a0 += o[0]; a1 += o[1]; a2 += o[2]; a3 += o[3]; ac += 1.0f;
        }
    }

    // Warp-segmented inclusive sum over per-thread suffix partials.
    unsigned lane = threadIdx.x & 31u;
    #pragma unroll
    for (int off = 1; off < 32; off <<= 1) {
        int   gg = __shfl_up_sync(0xFFFFFFFFu, gcur, off);
        float t0 = __shfl_up_sync(0xFFFFFFFFu, a0,   off);
        float t1 = __shfl_up_sync(0xFFFFFFFFu, a1,   off);
        float t2 = __shfl_up_sync(0xFFFFFFFFu, a2,   off);
        float t3 = __shfl_up_sync(0xFFFFFFFFu, a3,   off);
        float tc = __shfl_up_sync(0xFFFFFFFFu, ac,   off);
        if (lane >= (unsigned)off && gg == gcur) {
            a0 += t0; a1 += t1; a2 += t2; a3 += t3; ac += tc;
        }
    }
    int gnext = __shfl_down_sync(0xFFFFFFFFu, gcur, 1);
    bool last = (lane == 31u) || (gnext != gcur);
    if (last && gcur >= 0) {
        atomicAdd(&g_sums[gcur * 4 + 0], a0);
        atomicAdd(&g_sums[gcur * 4 + 1], a1);
        atomicAdd(&g_sums[gcur * 4 + 2], a2);
        atomicAdd(&g_sums[gcur * 4 + 3], a3);
        atomicAdd(&g_cnts[gcur], ac);
    }
}

// ---------------------------------------------------------------------------
// Kernel 3: mean pool + log_softmax; zeroes g_sums/g_cnts after consuming.
// ---------------------------------------------------------------------------
__global__ void k_pool(float* __restrict__ out) {
    int g = blockIdx.x * blockDim.x + threadIdx.x;
    if (g >= NUM_GRAPHS) return;
    float c = fmaxf(g_cnts[g], 1.0f);
    g_cnts[g] = 0.0f;
    float v[4];
    float m = -INFINITY;
    #pragma unroll
    for (int k = 0; k < 4; k++) {
        v[k] = g_sums[g * 4 + k] / c;
        g_sums[g * 4 + k] = 0.0f;
        m = fmaxf(m, v[k]);
    }
    float s = 0.0f;
    #pragma unroll
    for (int k = 0; k < 4; k++) s += expf(v[k] - m);
    float l = m + logf(s);
    #pragma unroll
    for (int k = 0; k < 4; k++) out[g * 4 + k] = v[k] - l;
}

// ---------------------------------------------------------------------------
extern "C" void kernel_launch(void* const* d_in, const int* in_sizes, int n_in,
                              void* d_out, int out_size) {
    const float4* x   = (const float4*)d_in[0];
    const int*    ei  = (const int*)   d_in[1];   // [2, E]
    const int*    bat = (const int*)   d_in[2];
    const float*  eps = (const float*) d_in[3];
    const float*  W1  = (const float*) d_in[4];
    const float*  b1  = (const float*) d_in[5];
    const float*  W2  = (const float*) d_in[6];
    const float*  b2  = (const float*) d_in[7];
    float* out = (float*)d_out;

    int E = in_sizes[1] / 2;
    const int* src = ei;
    const int* dst = ei + E;

    int octs  = E / 8 + 1;                  // +1 thread for the tail
    int quads = (N_NODES + 3) / 4;
    k_edge<<<(octs + 255) / 256, 256>>>(x, src, dst, E);
    k_node<<<(quads + 255) / 256, 256>>>(x, bat, eps, W1, b1, W2, b2);
    k_pool<<<(NUM_GRAPHS + 255) / 256, 256>>>(out);
}

// round 6
// speedup vs baseline: 1.0043x; 1.0021x over previous
#include <cuda_runtime.h>
#include <cuda_bf16.h>
#include <math.h>

#define N_NODES    500000
#define NUM_GRAPHS 1024

// Scratch (no cudaMalloc allowed). BSS-zeroed at load; self-cleaning per call.
__device__ float g_agg [N_NODES * 4];      // 8 MB, L2-resident
__device__ float g_sums[NUM_GRAPHS * 4];
__device__ float g_cnts[NUM_GRAPHS];

// ---------------------------------------------------------------------------
// Kernel 1: edge scatter  agg[dst] += x[src]
// 8 edges/thread: 2x int4 streaming index loads per side, 8 independent L2
// gathers in flight, one red.v4 (1 sector) per edge. L2-sector bound.
// ---------------------------------------------------------------------------
__global__ void __launch_bounds__(256) k_edge(const float4* __restrict__ x,
                                              const int*    __restrict__ src,
                                              const int*    __restrict__ dst,
                                              int E) {
    int q  = blockIdx.x * blockDim.x + threadIdx.x;   // octet index
    int Eo = E >> 3;                                   // full octets

    if (q < Eo) {
        const int4* s4p = reinterpret_cast<const int4*>(src) + 2 * q;
        const int4* d4p = reinterpret_cast<const int4*>(dst) + 2 * q;
        int4 sa = __ldcs(s4p);
        int4 sb = __ldcs(s4p + 1);
        int4 da = __ldcs(d4p);
        int4 db = __ldcs(d4p + 1);

        float4 v0 = __ldg(x + sa.x);
        float4 v1 = __ldg(x + sa.y);
        float4 v2 = __ldg(x + sa.z);
        float4 v3 = __ldg(x + sa.w);
        float4 v4 = __ldg(x + sb.x);
        float4 v5 = __ldg(x + sb.y);
        float4 v6 = __ldg(x + sb.z);
        float4 v7 = __ldg(x + sb.w);

        #define RED4(didx, v)                                                  \
            asm volatile("red.global.add.v4.f32 [%0], {%1, %2, %3, %4};"       \
                         :: "l"(&g_agg[(size_t)(didx) * 4]),                    \
                            "f"((v).x), "f"((v).y), "f"((v).z), "f"((v).w)      \
                         : "memory")
        RED4(da.x, v0); RED4(da.y, v1); RED4(da.z, v2); RED4(da.w, v3);
        RED4(db.x, v4); RED4(db.y, v5); RED4(db.z, v6); RED4(db.w, v7);
        #undef RED4
    } else if (q == Eo) {
        for (int i = Eo * 8; i < E; i++) {
            int s = __ldg(src + i);
            int d = __ldg(dst + i);
            float4 v = __ldg(x + s);
            asm volatile("red.global.add.v4.f32 [%0], {%1, %2, %3, %4};"
                         :: "l"(&g_agg[(size_t)d * 4]),
                            "f"(v.x), "f"(v.y), "f"(v.z), "f"(v.w) : "memory");
        }
    }
}

// ---------------------------------------------------------------------------
// Kernel 2: per-node MLP + pooled sum. 4 nodes/thread: accumulate locally
// (nodes in a thread almost always share a graph id since ~488 nodes/graph),
// flush rare intra-thread graph boundaries via direct atomics, then ONE
// warp-segmented scan over per-thread suffix partials.
// Self-cleaning: zeroes g_agg after consuming it.
// ---------------------------------------------------------------------------
__device__ __forceinline__ void mlp4(float h0, float h1, float h2, float h3,
                                     const float* sW1, const float* sb1,
                                     const float* sW2, const float* sb2,
                                     float o[4]) {
    float a[4];
    #pragma unroll
    for (int k = 0; k < 4; k++) a[k] = sb2[k];
    #pragma unroll
    for (int j = 0; j < 16; j++) {
        float tj = sb1[j]
                 + h0 * sW1[0 * 16 + j]
                 + h1 * sW1[1 * 16 + j]
                 + h2 * sW1[2 * 16 + j]
                 + h3 * sW1[3 * 16 + j];
        tj = fmaxf(tj, 0.0f);
        #pragma unroll
        for (int k = 0; k < 4; k++) a[k] += tj * sW2[j * 4 + k];
    }
    #pragma unroll
    for (int k = 0; k < 4; k++) o[k] = fmaxf(a[k], 0.0f);
}

__global__ void __launch_bounds__(256) k_node(const float4* __restrict__ x,
                       const int*    __restrict__ batch,
                       const float*  __restrict__ eps_p,
                       const float*  __restrict__ W1,   // [4,16]
                       const float*  __restrict__ b1,   // [16]
                       const float*  __restrict__ W2,   // [16,4]
                       const float*  __restrict__ b2) { // [4]
    __shared__ float sW1[64], sb1[16], sW2[64], sb2[4];
    __shared__ float seps;
    int t = threadIdx.x;
    if (t < 64)  sW1[t] = W1[t];
    if (t < 16)  sb1[t] = b1[t];
    if (t >= 64 && t < 128) sW2[t - 64] = W2[t - 64];
    if (t >= 128 && t < 132) sb2[t - 128] = b2[t - 128];
    if (t == 132) seps = 1.0f + eps_p[0];
    __syncthreads();

    int q = blockIdx.x * blockDim.x + threadIdx.x;   // quad-node index
    int base = q * 4;

    // per-thread running segment (suffix): graph id + accumulated outputs
    float a0 = 0.f, a1 = 0.f, a2 = 0.f, a3 = 0.f, ac = 0.f;
    int gcur = -1;

    if (base < N_NODES) {
        int nmax = N_NODES - base;
        if (nmax > 4) nmax = 4;
        int4 b4;
        if (nmax == 4) {
            b4 = __ldg(reinterpret_cast<const int4*>(batch) + q);
        } else {
            b4.x = b4.y = b4.z = b4.w = -1;
            int* bp = &b4.x;
            for (int n = 0; n < nmax; n++) bp[n] = __ldg(batch + base + n);
        }
        const int bids[4] = {b4.x, b4.y, b4.z, b4.w};
        float4* aggv = reinterpret_cast<float4*>(g_agg);
        float se = seps;

        #pragma unroll
        for (int n = 0; n < 4; n++) {
            if (n >= nmax) break;
            float4 xv = __ldg(x + base + n);
            float4 av = aggv[base + n];
            aggv[base + n] = make_float4(0.f, 0.f, 0.f, 0.f);
            float o[4];
            mlp4(se * xv.x + av.x, se * xv.y + av.y,
                 se * xv.z + av.z, se * xv.w + av.w,
                 sW1, sb1, sW2, sb2, o);
            int g = bids[n];
            if (g != gcur) {
                if (gcur >= 0) {   // rare intra-thread boundary: flush directly
                    atomicAdd(&g_sums[gcur * 4 + 0], a0);
                    atomicAdd(&g_sums[gcur * 4 + 1], a1);
                    atomicAdd(&g_sums[gcur * 4 + 2], a2);
                    atomicAdd(&g_sums[gcur * 4 + 3], a3);
                    atomicAdd(&g_cnts[gcur], ac);
                }
                gcur = g; a0 = a1 = a2 = a3 = ac = 0.f;
            }
            a0 += o[0]; a1 += o[1]; a2 += o[2]; a3 += o[3]; ac += 1.0f;
        }
    }

    // Warp-segmented inclusive sum over per-thread suffix partials.
    unsigned lane = threadIdx.x & 31u;
    #pragma unroll
    for (int off = 1; off < 32; off <<= 1) {
        int   gg = __shfl_up_sync(0xFFFFFFFFu, gcur, off);
        float t0 = __shfl_up_sync(0xFFFFFFFFu, a0,   off);
        float t1 = __shfl_up_sync(0xFFFFFFFFu, a1,   off);
        float t2 = __shfl_up_sync(0xFFFFFFFFu, a2,   off);
        float t3 = __shfl_up_sync(0xFFFFFFFFu, a3,   off);
        float tc = __shfl_up_sync(0xFFFFFFFFu, ac,   off);
        if (lane >= (unsigned)off && gg == gcur) {
            a0 += t0; a1 += t1; a2 += t2; a3 += t3; ac += tc;
        }
    }
    int gnext = __shfl_down_sync(0xFFFFFFFFu, gcur, 1);
    bool last = (lane == 31u) || (gnext != gcur);
    if (last && gcur >= 0) {
        atomicAdd(&g_sums[gcur * 4 + 0], a0);
        atomicAdd(&g_sums[gcur * 4 + 1], a1);
        atomicAdd(&g_sums[gcur * 4 + 2], a2);
        atomicAdd(&g_sums[gcur * 4 + 3], a3);
        atomicAdd(&g_cnts[gcur], ac);
    }
}

// ---------------------------------------------------------------------------
// Kernel 3: mean pool + log_softmax; zeroes g_sums/g_cnts after consuming.
// ---------------------------------------------------------------------------
__global__ void k_pool(float* __restrict__ out) {
    int g = blockIdx.x * blockDim.x + threadIdx.x;
    if (g >= NUM_GRAPHS) return;
    float c = fmaxf(g_cnts[g], 1.0f);
    g_cnts[g] = 0.0f;
    float v[4];
    float m = -INFINITY;
    #pragma unroll
    for (int k = 0; k < 4; k++) {
        v[k] = g_sums[g * 4 + k] / c;
        g_sums[g * 4 + k] = 0.0f;
        m = fmaxf(m, v[k]);
    }
    float s = 0.0f;
    #pragma unroll
    for (int k = 0; k < 4; k++) s += expf(v[k] - m);
    float l = m + logf(s);
    #pragma unroll
    for (int k = 0; k < 4; k++) out[g * 4 + k] = v[k] - l;
}

// ---------------------------------------------------------------------------
extern "C" void kernel_launch(void* const* d_in, const int* in_sizes, int n_in,
                              void* d_out, int out_size) {
    const float4* x   = (const float4*)d_in[0];
    const int*    ei  = (const int*)   d_in[1];   // [2, E]
    const int*    bat = (const int*)   d_in[2];
    const float*  eps = (const float*) d_in[3];
    const float*  W1  = (const float*) d_in[4];
    const float*  b1  = (const float*) d_in[5];
    const float*  W2  = (const float*) d_in[6];
    const float*  b2  = (const float*) d_in[7];
    float* out = (float*)d_out;

    int E = in_sizes[1] / 2;
    const int* src = ei;
    const int* dst = ei + E;

    int octs  = E / 8 + 1;                  // +1 thread for the tail
    int quads = (N_NODES + 3) / 4;
    k_edge<<<(octs + 255) / 256, 256>>>(x, src, dst, E);
    k_node<<<(quads + 255) / 256, 256>>>(x, bat, eps, W1, b1, W2, b2);
    k_pool<<<(NUM_GRAPHS + 255) / 256, 256>>>(out);
}